// round 12
// baseline (speedup 1.0000x reference)
#include <cuda_runtime.h>
#include <cuda_bf16.h>

// -------------------- scratch (no allocations allowed) --------------------
#define CAP 262144   // >= S*B*N = 204800

__device__ int g_pos [CAP];   // pos[inst*N + node_local] = tour position
__device__ int g_winf[CAP];   // min edge idx matching forward query at (inst,pos)
__device__ int g_winr[CAP];   // min edge idx matching reverse query at (inst,pos)

#define NOTFOUND 0x7fffffff

// -------------------- input identification (uniform, cached) --------------
__device__ __forceinline__ bool is64_arange(const unsigned* p) {
    return p[0]==0u && p[1]==0u && p[2]==1u && p[3]==0u &&
           p[4]==2u && p[5]==0u && p[6]==3u && p[7]==0u;
}
__device__ __forceinline__ bool is32_arange(const unsigned* p) {
    return p[0]==0u && p[1]==1u && p[2]==2u && p[3]==3u &&
           p[4]==4u && p[5]==5u && p[6]==6u && p[7]==7u;
}
// bit0 = pb is node_offset (so pa is y), bit1 = ints are 64-bit
__device__ __forceinline__ int detect_cfg(const unsigned* pa, const unsigned* pb) {
    if (is64_arange(pa)) return 2;
    if (is32_arange(pa)) return 0;
    if (is64_arange(pb)) return 3;
    return 1;
}

// -------------------- kernel A: inverse permutation + winner init ---------
// 2 INDEPENDENT elements per thread (j and j+T): doubles memory-level
// parallelism on the latency-bound y-load -> pos-scatter chain without
// creating a serial dependency chain (R9 lesson) and while keeping enough
// blocks resident (R9/R10 lesson).
__global__ void prep_kernel(const unsigned* __restrict__ pa,
                            const unsigned* __restrict__ pb,
                            int total, int N, int T) {
    int cfg = detect_cfg(pa, pb);
    const int* y = (const int*)((cfg & 1) ? pa : pb);

    int j0 = blockIdx.x * blockDim.x + threadIdx.x;
    if (j0 >= T) return;
    int j1 = j0 + T;

    // two independent loads issued back-to-back
    int y0 = y[j0];
    int y1 = (j1 < total) ? y[j1] : 0;

    int inst0 = j0 / N;
    int i0    = j0 - inst0 * N;
    g_pos [inst0 * N + y0] = i0;
    g_winf[j0] = NOTFOUND;
    g_winr[j0] = NOTFOUND;

    if (j1 < total) {
        int inst1 = j1 / N;
        int i1    = j1 - inst1 * N;
        g_pos [inst1 * N + y1] = i1;
        g_winf[j1] = NOTFOUND;
        g_winr[j1] = NOTFOUND;
    }
}

// -------------------- kernel B: scatter edges onto tour positions ---------
__global__ void match_kernel(const unsigned* __restrict__ pa,
                             const unsigned* __restrict__ pb,
                             const void* __restrict__ eidx,
                             int E, int N) {
    int cfg = detect_cfg(pa, pb);
    int e = blockIdx.x * blockDim.x + threadIdx.x;
    if (e >= E) return;

    unsigned s, d;
    if (cfg & 2) {
        const long long* p = (const long long*)eidx;
        s = (unsigned)p[e]; d = (unsigned)p[e + E];
    } else {
        const int* p = (const int*)eidx;
        s = (unsigned)p[e]; d = (unsigned)p[e + E];
    }
    unsigned uN = (unsigned)N;
    unsigned is = s / uN;
    unsigned id = d / uN;
    if (is != id) return;                 // cross-instance edge: can't match
    unsigned sl = s - is * uN;
    unsigned dl = d - id * uN;
    int base = (int)is * N;
    int ps = g_pos[base + sl];
    int pd = g_pos[base + dl];
    int psn = (ps + 1 == N) ? 0 : ps + 1;
    int pdn = (pd + 1 == N) ? 0 : pd + 1;
    if (psn == pd) atomicMin(&g_winf[base + ps], e);  // forward match at pos ps
    if (pdn == ps) atomicMin(&g_winr[base + pd], e);  // reverse match at pos pd
}

// -------------------- kernel C: gather + mean -----------------------------
// grid = S*B blocks, blockDim = 128 (4 warps). Warp w owns rows w, w+4, ...
// (exactly the R8 configuration — best measured)
__global__ void gather_kernel(const float* __restrict__ emb,
                              float* __restrict__ out,
                              int N, int EM) {
    __shared__ int   sidx[128];
    __shared__ float sacc[4 * 128];

    int inst = blockIdx.x;
    int t = threadIdx.x;
    int base = inst * N;

    if (t < N) {
        int vf = g_winf[base + t];
        int vr = g_winr[base + t];
        sidx[t] = (vf != NOTFOUND) ? vf : ((vr != NOTFOUND) ? vr : -1);
    }
    __syncthreads();

    if (EM == 128) {
        int w = t >> 5, l = t & 31;
        float4 acc = make_float4(0.f, 0.f, 0.f, 0.f);
        #pragma unroll 8
        for (int i = w; i < N; i += 4) {
            int v = sidx[i];
            if (v >= 0) {
                float4 x = ((const float4*)(emb + (long long)v * 128))[l];
                acc.x += x.x; acc.y += x.y; acc.z += x.z; acc.w += x.w;
            }
        }
        ((float4*)(sacc + w * 128))[l] = acc;
        __syncthreads();
        float s = sacc[t] + sacc[128 + t] + sacc[256 + t] + sacc[384 + t];
        out[(long long)inst * 128 + t] = s * (1.0f / (float)N);
    } else {
        if (t < EM) {
            float acc = 0.0f;
            for (int i = 0; i < N; i++) {
                int v = sidx[i];
                if (v >= 0) acc += emb[(long long)v * EM + t];
            }
            out[(long long)inst * EM + t] = acc * (1.0f / (float)N);
        }
    }
}

// -------------------- launcher --------------------------------------------
extern "C" void kernel_launch(void* const* d_in, const int* in_sizes, int n_in,
                              void* d_out, int out_size) {
    // Identify inputs by element count (robust to ordering):
    //   edge_emb -> largest, edge_index -> second, y/node_offset -> the pair.
    int order[16];
    for (int i = 0; i < n_in && i < 16; i++) order[i] = i;
    for (int i = 0; i < n_in; i++)
        for (int j = i + 1; j < n_in; j++)
            if (in_sizes[order[j]] > in_sizes[order[i]]) {
                int tmp = order[i]; order[i] = order[j]; order[j] = tmp;
            }
    int emb_i  = order[0];
    int eidx_i = order[1];
    int pa_i   = order[2];
    int pb_i   = order[3];

    const float*    emb  = (const float*)d_in[emb_i];
    const void*     eidx = d_in[eidx_i];
    const unsigned* pa   = (const unsigned*)d_in[pa_i];
    const unsigned* pb   = (const unsigned*)d_in[pb_i];
    float*          out  = (float*)d_out;

    int total = in_sizes[pa_i];                    // S*B*N
    int E  = in_sizes[eidx_i] / 2;
    int EM = in_sizes[emb_i] / E;                  // 128
    int inst = out_size / EM;                      // S*B
    int N = total / inst;                          // 100

    int T = (total + 1) / 2;
    prep_kernel <<<(T + 255) / 256, 256>>>(pa, pb, total, N, T);
    match_kernel<<<(E + 255) / 256, 256>>>(pa, pb, eidx, E, N);
    gather_kernel<<<inst, 128>>>(emb, out, N, EM);
}

// round 13
// speedup vs baseline: 1.1994x; 1.1994x over previous
#include <cuda_runtime.h>
#include <cuda_bf16.h>

// -------------------- scratch (no allocations allowed) --------------------
#define CAP 262144   // >= S*B*N = 204800

__device__ int g_pos [CAP];   // pos[inst*N + node_local] = tour position
__device__ int g_winf[CAP];   // min edge idx matching forward query at (inst,pos)
__device__ int g_winr[CAP];   // min edge idx matching reverse query at (inst,pos)

#define NOTFOUND 0x7fffffff

// -------------------- input identification (per-block, uniform) -----------
__device__ __forceinline__ bool is64_arange(const unsigned* p) {
    return p[0]==0u && p[1]==0u && p[2]==1u && p[3]==0u &&
           p[4]==2u && p[5]==0u && p[6]==3u && p[7]==0u;
}
__device__ __forceinline__ bool is32_arange(const unsigned* p) {
    return p[0]==0u && p[1]==1u && p[2]==2u && p[3]==3u &&
           p[4]==4u && p[5]==5u && p[6]==6u && p[7]==7u;
}
// returns (noff_is_b, w64) packed: bit0 = pb is node_offset, bit1 = ints are 64-bit
__device__ __forceinline__ int detect_cfg(const unsigned* pa, const unsigned* pb) {
    if (is64_arange(pa)) return 2;      // pa = noff, 64-bit
    if (is32_arange(pa)) return 0;      // pa = noff, 32-bit
    if (is64_arange(pb)) return 3;      // pb = noff, 64-bit
    return 1;                           // pb = noff, 32-bit
}

// -------------------- kernel A: inverse permutation + winner init ---------
__global__ void prep_kernel(const unsigned* __restrict__ pa,
                            const unsigned* __restrict__ pb,
                            int total, int N) {
    int cfg = detect_cfg(pa, pb);
    const int* y = (const int*)((cfg & 1) ? pa : pb);

    int j = blockIdx.x * blockDim.x + threadIdx.x;
    if (j >= total) return;
    int inst = j / N;
    int i    = j - inst * N;
    int yv   = y[j];                      // node local id, < N
    g_pos [inst * N + yv] = i;            // fully overwritten; no reset needed
    g_winf[j] = NOTFOUND;
    g_winr[j] = NOTFOUND;
}

// -------------------- kernel B: scatter edges onto tour positions ---------
__global__ void match_kernel(const unsigned* __restrict__ pa,
                             const unsigned* __restrict__ pb,
                             const void* __restrict__ eidx,
                             int E, int N) {
    int cfg = detect_cfg(pa, pb);
    int e = blockIdx.x * blockDim.x + threadIdx.x;
    if (e >= E) return;

    unsigned s, d;
    if (cfg & 2) {
        const long long* p = (const long long*)eidx;
        s = (unsigned)p[e]; d = (unsigned)p[e + E];
    } else {
        const int* p = (const int*)eidx;
        s = (unsigned)p[e]; d = (unsigned)p[e + E];
    }
    unsigned uN = (unsigned)N;
    unsigned is = s / uN;
    unsigned id = d / uN;
    if (is != id) return;                 // cross-instance edge: can't match
    unsigned sl = s - is * uN;
    unsigned dl = d - id * uN;
    int base = (int)is * N;
    int ps = g_pos[base + sl];
    int pd = g_pos[base + dl];
    int psn = (ps + 1 == N) ? 0 : ps + 1;
    int pdn = (pd + 1 == N) ? 0 : pd + 1;
    if (psn == pd) atomicMin(&g_winf[base + ps], e);  // forward match at pos ps
    if (pdn == ps) atomicMin(&g_winr[base + pd], e);  // reverse match at pos pd
}

// -------------------- kernel C: gather + mean -----------------------------
// grid = S*B blocks, blockDim = 128 (4 warps). Warp w owns rows w, w+4, ...
__global__ void gather_kernel(const float* __restrict__ emb,
                              float* __restrict__ out,
                              int N, int EM) {
    __shared__ int   sidx[128];
    __shared__ float sacc[4 * 128];

    int inst = blockIdx.x;
    int t = threadIdx.x;
    int base = inst * N;

    if (t < N) {
        int vf = g_winf[base + t];
        int vr = g_winr[base + t];
        sidx[t] = (vf != NOTFOUND) ? vf : ((vr != NOTFOUND) ? vr : -1);
    }
    __syncthreads();

    if (EM == 128) {
        int w = t >> 5, l = t & 31;
        float4 acc = make_float4(0.f, 0.f, 0.f, 0.f);
        #pragma unroll 8
        for (int i = w; i < N; i += 4) {
            int v = sidx[i];
            if (v >= 0) {
                float4 x = ((const float4*)(emb + (long long)v * 128))[l];
                acc.x += x.x; acc.y += x.y; acc.z += x.z; acc.w += x.w;
            }
        }
        ((float4*)(sacc + w * 128))[l] = acc;
        __syncthreads();
        float s = sacc[t] + sacc[128 + t] + sacc[256 + t] + sacc[384 + t];
        out[(long long)inst * 128 + t] = s * (1.0f / (float)N);
    } else {
        if (t < EM) {
            float acc = 0.0f;
            for (int i = 0; i < N; i++) {
                int v = sidx[i];
                if (v >= 0) acc += emb[(long long)v * EM + t];
            }
            out[(long long)inst * EM + t] = acc * (1.0f / (float)N);
        }
    }
}

// -------------------- launcher --------------------------------------------
extern "C" void kernel_launch(void* const* d_in, const int* in_sizes, int n_in,
                              void* d_out, int out_size) {
    // Identify inputs by element count (robust to ordering):
    //   edge_emb -> largest, edge_index -> second, y/node_offset -> the pair.
    int order[16];
    for (int i = 0; i < n_in && i < 16; i++) order[i] = i;
    for (int i = 0; i < n_in; i++)
        for (int j = i + 1; j < n_in; j++)
            if (in_sizes[order[j]] > in_sizes[order[i]]) {
                int tmp = order[i]; order[i] = order[j]; order[j] = tmp;
            }
    int emb_i  = order[0];
    int eidx_i = order[1];
    int pa_i   = order[2];
    int pb_i   = order[3];

    const float*    emb  = (const float*)d_in[emb_i];
    const void*     eidx = d_in[eidx_i];
    const unsigned* pa   = (const unsigned*)d_in[pa_i];
    const unsigned* pb   = (const unsigned*)d_in[pb_i];
    float*          out  = (float*)d_out;

    int total = in_sizes[pa_i];                    // S*B*N
    int E  = in_sizes[eidx_i] / 2;
    int EM = in_sizes[emb_i] / E;                  // 128
    int inst = out_size / EM;                      // S*B
    int N = total / inst;                          // 100

    prep_kernel <<<(total + 255) / 256, 256>>>(pa, pb, total, N);
    match_kernel<<<(E + 255) / 256, 256>>>(pa, pb, eidx, E, N);
    gather_kernel<<<inst, 128>>>(emb, out, N, EM);
}

// round 14
// speedup vs baseline: 1.2394x; 1.0334x over previous
#include <cuda_runtime.h>
#include <cuda_bf16.h>

// -------------------- scratch (no allocations allowed) --------------------
#define CAP 262144   // >= S*B*N = 204800

__device__ int g_pos[CAP];   // pos[inst*N + node_local] = tour position
__device__ int g_win[CAP];   // packed winner: e | (is_reverse << 30); min =
                             // forward-precedence + min-edge-index semantics

#define NOTFOUND 0x7fffffff
#define REVBIT   0x40000000
#define EMASK    0x3fffffff

// -------------------- input identification (per-block, uniform) -----------
__device__ __forceinline__ bool is64_arange(const unsigned* p) {
    return p[0]==0u && p[1]==0u && p[2]==1u && p[3]==0u &&
           p[4]==2u && p[5]==0u && p[6]==3u && p[7]==0u;
}
__device__ __forceinline__ bool is32_arange(const unsigned* p) {
    return p[0]==0u && p[1]==1u && p[2]==2u && p[3]==3u &&
           p[4]==4u && p[5]==5u && p[6]==6u && p[7]==7u;
}
// bit0 = pb is node_offset (so pa is y), bit1 = ints are 64-bit
__device__ __forceinline__ int detect_cfg(const unsigned* pa, const unsigned* pb) {
    if (is64_arange(pa)) return 2;
    if (is32_arange(pa)) return 0;
    if (is64_arange(pb)) return 3;
    return 1;
}

// fast exact division by N for dividends < 2^32 / N (magic = 2^32/N + 1)
__device__ __forceinline__ unsigned fdiv(unsigned j, unsigned magic) {
    return __umulhi(j, magic);
}

// -------------------- kernel A: inverse permutation + winner init ---------
__global__ void prep_kernel(const unsigned* __restrict__ pa,
                            const unsigned* __restrict__ pb,
                            int total, int N, unsigned magic) {
    int cfg = detect_cfg(pa, pb);
    const int* y = (const int*)((cfg & 1) ? pa : pb);

    int j = blockIdx.x * blockDim.x + threadIdx.x;
    if (j >= total) return;
    unsigned inst = fdiv((unsigned)j, magic);
    int i = j - (int)inst * N;
    g_pos[(int)inst * N + y[j]] = i;      // fully overwritten; no reset needed
    g_win[j] = NOTFOUND;
}

// -------------------- kernel B: scatter edges onto tour positions ---------
__global__ void match_kernel(const unsigned* __restrict__ pa,
                             const unsigned* __restrict__ pb,
                             const void* __restrict__ eidx,
                             int E, int N, unsigned magic) {
    int cfg = detect_cfg(pa, pb);
    int e = blockIdx.x * blockDim.x + threadIdx.x;
    if (e >= E) return;

    unsigned s, d;
    if (cfg & 2) {
        const long long* p = (const long long*)eidx;
        s = (unsigned)p[e]; d = (unsigned)p[e + E];
    } else {
        const int* p = (const int*)eidx;
        s = (unsigned)p[e]; d = (unsigned)p[e + E];
    }
    unsigned uN = (unsigned)N;
    unsigned is = fdiv(s, magic);
    unsigned id = fdiv(d, magic);
    if (is != id) return;                 // cross-instance edge: can't match
    unsigned sl = s - is * uN;
    unsigned dl = d - id * uN;
    int base = (int)is * N;
    int ps = g_pos[base + sl];
    int pd = g_pos[base + dl];
    int psn = (ps + 1 == N) ? 0 : ps + 1;
    int pdn = (pd + 1 == N) ? 0 : pd + 1;
    // forward match at position ps: value = e (always < any reverse value)
    if (psn == pd) atomicMin(&g_win[base + ps], e);
    // reverse match at position pd: value = e | REVBIT
    if (pdn == ps) atomicMin(&g_win[base + pd], e | REVBIT);
}

// -------------------- kernel C: gather + mean -----------------------------
// grid = S*B blocks, blockDim = 128 (4 warps). Warp w owns rows w, w+4, ...
__global__ void gather_kernel(const float* __restrict__ emb,
                              float* __restrict__ out,
                              int N, int EM) {
    __shared__ int   sidx[128];
    __shared__ float sacc[4 * 128];

    int inst = blockIdx.x;
    int t = threadIdx.x;
    int base = inst * N;

    if (t < N) {
        int v = g_win[base + t];
        sidx[t] = (v == NOTFOUND) ? -1 : (v & EMASK);
    }
    __syncthreads();

    if (EM == 128) {
        int w = t >> 5, l = t & 31;
        float4 acc = make_float4(0.f, 0.f, 0.f, 0.f);
        #pragma unroll 8
        for (int i = w; i < N; i += 4) {
            int v = sidx[i];
            if (v >= 0) {
                float4 x = ((const float4*)(emb + (long long)v * 128))[l];
                acc.x += x.x; acc.y += x.y; acc.z += x.z; acc.w += x.w;
            }
        }
        ((float4*)(sacc + w * 128))[l] = acc;
        __syncthreads();
        float s = sacc[t] + sacc[128 + t] + sacc[256 + t] + sacc[384 + t];
        out[(long long)inst * 128 + t] = s * (1.0f / (float)N);
    } else {
        if (t < EM) {
            float acc = 0.0f;
            for (int i = 0; i < N; i++) {
                int v = sidx[i];
                if (v >= 0) acc += emb[(long long)v * EM + t];
            }
            out[(long long)inst * EM + t] = acc * (1.0f / (float)N);
        }
    }
}

// -------------------- launcher --------------------------------------------
extern "C" void kernel_launch(void* const* d_in, const int* in_sizes, int n_in,
                              void* d_out, int out_size) {
    // Identify inputs by element count (robust to ordering):
    //   edge_emb -> largest, edge_index -> second, y/node_offset -> the pair.
    int order[16];
    for (int i = 0; i < n_in && i < 16; i++) order[i] = i;
    for (int i = 0; i < n_in; i++)
        for (int j = i + 1; j < n_in; j++)
            if (in_sizes[order[j]] > in_sizes[order[i]]) {
                int tmp = order[i]; order[i] = order[j]; order[j] = tmp;
            }
    int emb_i  = order[0];
    int eidx_i = order[1];
    int pa_i   = order[2];
    int pb_i   = order[3];

    const float*    emb  = (const float*)d_in[emb_i];
    const void*     eidx = d_in[eidx_i];
    const unsigned* pa   = (const unsigned*)d_in[pa_i];
    const unsigned* pb   = (const unsigned*)d_in[pb_i];
    float*          out  = (float*)d_out;

    int total = in_sizes[pa_i];                    // S*B*N
    int E  = in_sizes[eidx_i] / 2;
    int EM = in_sizes[emb_i] / E;                  // 128
    int inst = out_size / EM;                      // S*B
    int N = total / inst;                          // 100

    // magic for exact unsigned division by N (valid for dividends < 2^32/N)
    unsigned magic = (unsigned)(0x100000000ULL / (unsigned)N + 1ULL);

    prep_kernel <<<(total + 255) / 256, 256>>>(pa, pb, total, N, magic);
    match_kernel<<<(E + 255) / 256, 256>>>(pa, pb, eidx, E, N, magic);
    gather_kernel<<<inst, 128>>>(emb, out, N, EM);
}